// round 16
// baseline (speedup 1.0000x reference)
#include <cuda_runtime.h>
#include <math.h>
#include <cmath>

#define NB 128
#define NC 3
#define FS 8

// scratch (no allocations allowed)
__device__ float g_dct[NB * NC * 64];     // dct_in  [128,3,8,8]
__device__ float g_grad[NB * NC * 64];    // grad_in [128,3,8,8]

// Combined DCT-project + bilinear-resize operator, passed by value (8KB param).
struct AParam { float A[8 * 256]; };

// ---------------------------------------------------------------------------
// Kernel 1: per image (b,c): stream X once.
//  - T = A @ X (thread t owns column t, 8 accumulators, 16-row unroll)
//  - branchless stash of the 32 Sobel rows (rows 32g+14..17)
//  - epilogue: dct_in = T @ A^T (warp-parallel), grad_in = Sobel magnitude
// ---------------------------------------------------------------------------
__global__ __launch_bounds__(256) void dct_grad_kernel(const float* __restrict__ x,
                                                       const AParam P) {
    __shared__ float sA[2048];        //  8x256
    __shared__ float sRows[32][256];  // grad rows
    __shared__ float sT[2048];        //  8x256

    int img = blockIdx.x;
    const float* __restrict__ X = x + (size_t)img * 65536;
    int t = threadIdx.x;

    for (int i = t; i < 2048; i += 256) sA[i] = P.A[i];
    __syncthreads();

    const float4* __restrict__ sA4 = (const float4*)sA;

    float acc[8];
#pragma unroll
    for (int i = 0; i < 8; i++) acc[i] = 0.f;

    for (int h = 0; h < 256; h += 16) {
        float v[16];
#pragma unroll
        for (int u = 0; u < 16; u++) v[u] = X[(h + u) * 256 + t];
        // branchless stash: h%32==0 -> rows 4g+0,1 <- v[14],v[15] (rows 32g+14,15)
        //                   h%32==16 -> rows 4g+2,3 <- v[0], v[1]  (rows 32g+16,17)
        int g = h >> 5, half = (h >> 4) & 1;
        int base = g * 4 + half * 2;
        int src = half ? 0 : 14;
        sRows[base + 0][t] = v[src + 0];
        sRows[base + 1][t] = v[src + 1];
#pragma unroll
        for (int i = 0; i < 8; i++) {
#pragma unroll
            for (int q = 0; q < 4; q++) {
                float4 a = sA4[i * 64 + (h >> 2) + q];
                acc[i] += a.x * v[q * 4 + 0];
                acc[i] += a.y * v[q * 4 + 1];
                acc[i] += a.z * v[q * 4 + 2];
                acc[i] += a.w * v[q * 4 + 3];
            }
        }
    }
#pragma unroll
    for (int i = 0; i < 8; i++) sT[i * 256 + t] = acc[i];
    __syncthreads();

    int j = t >> 5;
    int lane = t & 31;
    int k = lane & 7, q = lane >> 3;
    const float4* T4 = (const float4*)(sT + j * 256);
    const float4* A4 = (const float4*)(sA + k * 256);
    float s = 0.f;
#pragma unroll
    for (int m = 0; m < 16; m++) {
        float4 tv = T4[q * 16 + m];
        float4 av = A4[q * 16 + m];
        s += tv.x * av.x + tv.y * av.y + tv.z * av.z + tv.w * av.w;
    }
    s += __shfl_xor_sync(0xffffffffu, s, 8);
    s += __shfl_xor_sync(0xffffffffu, s, 16);
    if (lane < 8) {
        g_dct[img * 64 + j * 8 + lane] = s;

        int kk = lane;
        float gsum = 0.f;
#pragma unroll
        for (int pr = 1; pr <= 2; pr++) {
#pragma unroll
            for (int pc = 0; pc < 2; pc++) {
                int c = 32 * kk + 15 + pc;
                int rb = j * 4 + pr;
                float p00 = sRows[rb - 1][c - 1], p01 = sRows[rb - 1][c], p02 = sRows[rb - 1][c + 1];
                float p10 = sRows[rb][c - 1],                              p12 = sRows[rb][c + 1];
                float p20 = sRows[rb + 1][c - 1], p21 = sRows[rb + 1][c], p22 = sRows[rb + 1][c + 1];
                float gx = (p02 - p00) + 2.f * (p12 - p10) + (p22 - p20);
                float gy = (p20 + 2.f * p21 + p22) - (p00 + 2.f * p01 + p02);
                gsum += sqrtf(gx * gx + gy * gy);
            }
        }
        g_grad[img * 64 + j * 8 + kk] = 0.25f * gsum;
    }
}

// ---------------------------------------------------------------------------
// Kernel 2: thread t owns oc = t>>2; quarter q = t&3 owns output rows 2q,2q+1
// (16 pixels). Conv weights register-cached; inner loop LDS+FFMA only.
// ---------------------------------------------------------------------------
__global__ __launch_bounds__(256) void head_kernel(
    const float* __restrict__ cwd, const float* __restrict__ cbd,
    const float* __restrict__ gnd, const float* __restrict__ btd,
    const float* __restrict__ cwg, const float* __restrict__ cbg,
    const float* __restrict__ gng, const float* __restrict__ btg,
    const float* __restrict__ fw,  const float* __restrict__ fb,
    const float* __restrict__ clw, const float* __restrict__ clb,
    float* __restrict__ out)
{
    __shared__ float sid[3][10][10];
    __shared__ float sig[3][10][10];
    __shared__ float swd[1728];   // conv_dct_w  [64][3][3][3]
    __shared__ float swg[1728];   // conv_grad_w
    __shared__ float red0[8], red1[8], red2[8];
    __shared__ float s_w;

    int b = blockIdx.x;
    int t = threadIdx.x;
    int oc = t >> 2, q = t & 3;

    for (int i = t; i < 300; i += 256) { (&sid[0][0][0])[i] = 0.f; (&sig[0][0][0])[i] = 0.f; }
    for (int i = t; i < 1728; i += 256) { swd[i] = cwd[i]; swg[i] = cwg[i]; }
    __syncthreads();
    for (int i = t; i < 192; i += 256) {
        int ic = i >> 6, pix = i & 63, r = pix >> 3, c = pix & 7;
        sid[ic][r + 1][c + 1] = g_dct[b * 192 + i];
        sig[ic][r + 1][c + 1] = g_grad[b * 192 + i];
    }
    __syncthreads();

    float wd[27], wg[27];
#pragma unroll
    for (int w = 0; w < 27; w++) { wd[w] = swd[oc * 27 + w]; wg[w] = swg[oc * 27 + w]; }

    const float inv = rsqrtf(1.f + 1e-5f);
    float scd = __ldg(&gnd[oc]) * inv;
    float ofd = __ldg(&cbd[oc]) * scd + __ldg(&btd[oc]);
    float scg = __ldg(&gng[oc]) * inv;
    float ofg = __ldg(&cbg[oc]) * scg + __ldg(&btg[oc]);
    float fwo = __ldg(&fw[oc]);

    float dvals[16], gvals[16];
    float pf = 0.f;
#pragma unroll
    for (int p = 0; p < 16; p++) {
        int r = 2 * q + (p >> 3), c = p & 7;
        float ad = 0.f, ag = 0.f;
#pragma unroll
        for (int ic = 0; ic < 3; ic++)
#pragma unroll
            for (int kh = 0; kh < 3; kh++)
#pragma unroll
                for (int kw = 0; kw < 3; kw++) {
                    int wi = (ic * 3 + kh) * 3 + kw;
                    ad += sid[ic][r + kh][c + kw] * wd[wi];
                    ag += sig[ic][r + kh][c + kw] * wg[wi];
                }
        ad = fmaxf(ad * scd + ofd, 0.f);
        ag = fmaxf(ag * scg + ofg, 0.f);
        dvals[p] = ad; gvals[p] = ag;
        pf += fwo * (ad + ag);
    }
    for (int o = 16; o > 0; o >>= 1) pf += __shfl_down_sync(0xffffffff, pf, o);
    if ((t & 31) == 0) red2[t >> 5] = pf;
    __syncthreads();
    if (t == 0) {
        float s = 0.f;
        for (int i = 0; i < 8; i++) s += red2[i];
        s = s * (1.f / 64.f) + fb[0];
        s_w = 1.f / (1.f + expf(-s));
    }
    __syncthreads();
    float w = s_w;

    float p0 = 0.f, p1 = 0.f;
#pragma unroll
    for (int p = 0; p < 16; p++) {
        int r = 2 * q + (p >> 3), c = p & 7;
        int flat = oc * 64 + r * 8 + c;
        float f = w * dvals[p] + (1.f - w) * gvals[p];
        p0 += __ldg(&clw[flat]) * f;
        p1 += __ldg(&clw[4096 + flat]) * f;
    }
    for (int o = 16; o > 0; o >>= 1) {
        p0 += __shfl_down_sync(0xffffffff, p0, o);
        p1 += __shfl_down_sync(0xffffffff, p1, o);
    }
    if ((t & 31) == 0) { red0[t >> 5] = p0; red1[t >> 5] = p1; }
    __syncthreads();
    if (t == 0) {
        float a = 0.f, c = 0.f;
        for (int i = 0; i < 8; i++) { a += red0[i]; c += red1[i]; }
        out[b * 2 + 0] = a + clb[0];
        out[b * 2 + 1] = c + clb[1];
    }
}

extern "C" void kernel_launch(void* const* d_in, const int* in_sizes, int n_in,
                              void* d_out, int out_size) {
    const float* x = (const float*)d_in[0];

    // Host-side A (double precision): deterministic, recomputed every call.
    static AParam P;
    const double PI = 3.14159265358979323846;
    const double srow = std::sqrt(2.0 / 256.0);
    for (int a = 0; a < 8; a++) {
        int r0 = 32 * a + 15, r1 = 32 * a + 16;
        for (int n = 0; n < 256; n++) {
            double acc = 0.0;
            for (int h = 0; h < 25; h++) {
                double sh = (h == 0) ? std::sqrt(1.0 / 256.0) : srow;
                double f = 2.0 * h + 1.0;
                double Bah = 0.5 * srow * (std::cos(PI * f * r0 / 512.0) +
                                           std::cos(PI * f * r1 / 512.0));
                acc += Bah * sh * std::cos(PI * (2.0 * n + 1.0) * h / 512.0);
            }
            P.A[a * 256 + n] = (float)acc;
        }
    }

    dct_grad_kernel<<<NB * NC, 256>>>(x, P);
    head_kernel<<<NB, 256>>>(
        (const float*)d_in[1], (const float*)d_in[2], (const float*)d_in[3], (const float*)d_in[4],
        (const float*)d_in[5], (const float*)d_in[6], (const float*)d_in[7], (const float*)d_in[8],
        (const float*)d_in[9], (const float*)d_in[10], (const float*)d_in[11], (const float*)d_in[12],
        (float*)d_out);
}